// round 12
// baseline (speedup 1.0000x reference)
#include <cuda_runtime.h>
#include <cstdint>

// KVQuantizer: feat [1, 32, 8192, 128] f32 -> same shape.
// Per chunk of 16 tokens (per head): row0 -> 8-bit asym quant (base);
// rows 1..15: diff = x - base_deq, 4-bit asym quant, zero the 64
// smallest-|deq| per 128-group with lowest-index tie-break, out = base + pruned.
// Bit-matches XLA:GPU: f32 divide -> div.full.f32, deq = fma(q,s,mn), rint.
// R12: k2 with 3 independent rows per warp (rows 1+j, 6+j, 11+j of ONE chunk;
// 5 warps/chunk) -- ILP 3 to fill the 28% idle alu issue slots; single shared
// base load per warp.

#define WFULL 0xFFFFFFFFu

__device__ __forceinline__ float div_full(float a, float b) {
    float r;
    asm("div.full.f32 %0, %1, %2;" : "=f"(r) : "f"(a), "f"(b));
    return r;
}
__device__ __forceinline__ int f2key(float x) {
    int u = __float_as_int(x);
    return u ^ ((u >> 31) & 0x7fffffff);
}
__device__ __forceinline__ float key2f(int k) {
    return __int_as_float(k ^ ((k >> 31) & 0x7fffffff));
}
__device__ __forceinline__ int redux_min_i(int v) {
    int r; asm("redux.sync.min.s32 %0, %1, 0xffffffff;" : "=r"(r) : "r"(v)); return r;
}
__device__ __forceinline__ int redux_max_i(int v) {
    int r; asm("redux.sync.max.s32 %0, %1, 0xffffffff;" : "=r"(r) : "r"(v)); return r;
}
__device__ __forceinline__ unsigned redux_add_u(unsigned v) {
    unsigned r; asm("redux.sync.add.u32 %0, %1, 0xffffffff;" : "=r"(r) : "r"(v)); return r;
}
__device__ __forceinline__ float warp_min_f(float x) { return key2f(redux_min_i(f2key(x))); }
__device__ __forceinline__ float warp_max_f(float x) { return key2f(redux_max_i(f2key(x))); }

__device__ __forceinline__ float quant_deq(float x, float mn, float s, float qmax, float& qf) {
    float t = div_full(__fsub_rn(x, mn), s);
    qf = fminf(fmaxf(rintf(t), 0.0f), qmax);
    return __fmaf_rn(qf, s, mn);
}

// ---- Kernel 1: all 16384 base rows. Warp handles 2 chunks (A, B) for ILP.
__global__ __launch_bounds__(256)
void kvq_base_kernel(const float* __restrict__ in, float* __restrict__ out) {
    int flat = (blockIdx.x << 3) + (threadIdx.x >> 5);   // warp id in [0, 8192)
    int lane = threadIdx.x & 31;
    const float4* in4  = reinterpret_cast<const float4*>(in);
    float4*       out4 = reinterpret_cast<float4*>(out);
    unsigned ia = ((unsigned)flat << 10) | (unsigned)lane;   // chunk 2*flat row0
    unsigned ib = ia + 512u;                                  // chunk 2*flat+1 row0

    float4 vA = in4[ia];
    float4 vB = in4[ib];

    float mnA = warp_min_f(fminf(fminf(vA.x, vA.y), fminf(vA.z, vA.w)));
    float mnB = warp_min_f(fminf(fminf(vB.x, vB.y), fminf(vB.z, vB.w)));
    float mxA = warp_max_f(fmaxf(fmaxf(vA.x, vA.y), fmaxf(vA.z, vA.w)));
    float mxB = warp_max_f(fmaxf(fmaxf(vB.x, vB.y), fmaxf(vB.z, vB.w)));
    float sA = fmaxf(div_full(__fsub_rn(mxA, mnA), 255.0f), 1e-5f);
    float sB = fmaxf(div_full(__fsub_rn(mxB, mnB), 255.0f), 1e-5f);
    float qf;
    float4 bA, bB;
    bA.x = quant_deq(vA.x, mnA, sA, 255.0f, qf);
    bB.x = quant_deq(vB.x, mnB, sB, 255.0f, qf);
    bA.y = quant_deq(vA.y, mnA, sA, 255.0f, qf);
    bB.y = quant_deq(vB.y, mnB, sB, 255.0f, qf);
    bA.z = quant_deq(vA.z, mnA, sA, 255.0f, qf);
    bB.z = quant_deq(vB.z, mnB, sB, 255.0f, qf);
    bA.w = quant_deq(vA.w, mnA, sA, 255.0f, qf);
    bB.w = quant_deq(vB.w, mnB, sB, 255.0f, qf);
    // Row 0 output is exactly base_deq (zero diff quantizes to exactly 0).
    out4[ia] = bA;
    out4[ib] = bB;
}

// ---- Kernel 2: 245760 diff rows. Warp handles rows 1+j, 6+j, 11+j (j=flat%5)
// of chunk flat/5 -- three independent chains (A, B, C) interleaved for ILP.
// Base read back from out (row-0 slot, L2-resident), shared by all 3 chains.
__global__ __launch_bounds__(256)
void kvq_diff_kernel(const float* __restrict__ in, float* __restrict__ out) {
    int flat = (blockIdx.x << 3) + (threadIdx.x >> 5);   // [0, 81920)
    int lane = threadIdx.x & 31;
    int c = flat / 5;                   // chunk index [0, 16384)
    int j = flat - c * 5;               // warp slot 0..4

    const float4* in4  = reinterpret_cast<const float4*>(in);
    float4*       out4 = reinterpret_cast<float4*>(out);
    unsigned c0 = ((unsigned)c << 9) | (unsigned)lane;    // chunk row0
    unsigned ia = c0 + (((unsigned)j +  1u) << 5);        // row 1+j
    unsigned ib = c0 + (((unsigned)j +  6u) << 5);        // row 6+j
    unsigned ic = c0 + (((unsigned)j + 11u) << 5);        // row 11+j

    // Issue all loads up front (base comes from out, written by kernel 1).
    float4 vA = in4[ia];
    float4 vB = in4[ib];
    float4 vC = in4[ic];
    float4 bb = out4[c0];

    float dA0 = __fsub_rn(vA.x, bb.x), dB0 = __fsub_rn(vB.x, bb.x), dC0 = __fsub_rn(vC.x, bb.x);
    float dA1 = __fsub_rn(vA.y, bb.y), dB1 = __fsub_rn(vB.y, bb.y), dC1 = __fsub_rn(vC.y, bb.y);
    float dA2 = __fsub_rn(vA.z, bb.z), dB2 = __fsub_rn(vB.z, bb.z), dC2 = __fsub_rn(vC.z, bb.z);
    float dA3 = __fsub_rn(vA.w, bb.w), dB3 = __fsub_rn(vB.w, bb.w), dC3 = __fsub_rn(vC.w, bb.w);

    float mnA = warp_min_f(fminf(fminf(dA0, dA1), fminf(dA2, dA3)));
    float mnB = warp_min_f(fminf(fminf(dB0, dB1), fminf(dB2, dB3)));
    float mnC = warp_min_f(fminf(fminf(dC0, dC1), fminf(dC2, dC3)));
    float mxA = warp_max_f(fmaxf(fmaxf(dA0, dA1), fmaxf(dA2, dA3)));
    float mxB = warp_max_f(fmaxf(fmaxf(dB0, dB1), fmaxf(dB2, dB3)));
    float mxC = warp_max_f(fmaxf(fmaxf(dC0, dC1), fmaxf(dC2, dC3)));
    float sA  = fmaxf(div_full(__fsub_rn(mxA, mnA), 15.0f), 1e-5f);
    float sB  = fmaxf(div_full(__fsub_rn(mxB, mnB), 15.0f), 1e-5f);
    float sC  = fmaxf(div_full(__fsub_rn(mxC, mnC), 15.0f), 1e-5f);

    float qA0f, qA1f, qA2f, qA3f, qB0f, qB1f, qB2f, qB3f, qC0f, qC1f, qC2f, qC3f;
    float eA0 = quant_deq(dA0, mnA, sA, 15.0f, qA0f);
    float eB0 = quant_deq(dB0, mnB, sB, 15.0f, qB0f);
    float eC0 = quant_deq(dC0, mnC, sC, 15.0f, qC0f);
    float eA1 = quant_deq(dA1, mnA, sA, 15.0f, qA1f);
    float eB1 = quant_deq(dB1, mnB, sB, 15.0f, qB1f);
    float eC1 = quant_deq(dC1, mnC, sC, 15.0f, qC1f);
    float eA2 = quant_deq(dA2, mnA, sA, 15.0f, qA2f);
    float eB2 = quant_deq(dB2, mnB, sB, 15.0f, qB2f);
    float eC2 = quant_deq(dC2, mnC, sC, 15.0f, qC2f);
    float eA3 = quant_deq(dA3, mnA, sA, 15.0f, qA3f);
    float eB3 = quant_deq(dB3, mnB, sB, 15.0f, qB3f);
    float eC3 = quant_deq(dC3, mnC, sC, 15.0f, qC3f);
    int qA0 = (int)qA0f, qA1 = (int)qA1f, qA2 = (int)qA2f, qA3 = (int)qA3f;
    int qB0 = (int)qB0f, qB1 = (int)qB1f, qB2 = (int)qB2f, qB3 = (int)qB3f;
    int qC0 = (int)qC0f, qC1 = (int)qC1f, qC2 = (int)qC2f, qC3 = (int)qC3f;

    // ---- Histograms: unpredicated u64 nibble accumulators ----
    unsigned long long hhA = (1ULL << (qA0 << 2)) + (1ULL << (qA1 << 2))
                           + (1ULL << (qA2 << 2)) + (1ULL << (qA3 << 2));
    unsigned long long hhB = (1ULL << (qB0 << 2)) + (1ULL << (qB1 << 2))
                           + (1ULL << (qB2 << 2)) + (1ULL << (qB3 << 2));
    unsigned long long hhC = (1ULL << (qC0 << 2)) + (1ULL << (qC1 << 2))
                           + (1ULL << (qC2 << 2)) + (1ULL << (qC3 << 2));
    unsigned loA = (unsigned)hhA, hiA = (unsigned)(hhA >> 32);
    unsigned loB = (unsigned)hhB, hiB = (unsigned)(hhB >> 32);
    unsigned loC = (unsigned)hhC, hiC = (unsigned)(hhC >> 32);
    unsigned hE0A = redux_add_u( loA       & 0x0F0F0F0Fu);
    unsigned hE0B = redux_add_u( loB       & 0x0F0F0F0Fu);
    unsigned hE0C = redux_add_u( loC       & 0x0F0F0F0Fu);
    unsigned hO0A = redux_add_u((loA >> 4) & 0x0F0F0F0Fu);
    unsigned hO0B = redux_add_u((loB >> 4) & 0x0F0F0F0Fu);
    unsigned hO0C = redux_add_u((loC >> 4) & 0x0F0F0F0Fu);
    unsigned hE1A = redux_add_u( hiA       & 0x0F0F0F0Fu);
    unsigned hE1B = redux_add_u( hiB       & 0x0F0F0F0Fu);
    unsigned hE1C = redux_add_u( hiC       & 0x0F0F0F0Fu);
    unsigned hO1A = redux_add_u((hiA >> 4) & 0x0F0F0F0Fu);
    unsigned hO1B = redux_add_u((hiB >> 4) & 0x0F0F0F0Fu);
    unsigned hO1C = redux_add_u((hiC >> 4) & 0x0F0F0F0Fu);

    // Mirrored levels: lanes l and l+16 both own level (l & 15).
    int lvl = lane & 15;
    float alvA = fabsf(__fmaf_rn((float)lvl, sA, mnA));
    float alvB = fabsf(__fmaf_rn((float)lvl, sB, mnB));
    float alvC = fabsf(__fmaf_rn((float)lvl, sC, mnC));

    // Halved Cle scan, shuffle-free: lanes<16 scan levels [0,8), lanes>=16 [8,16).
    bool hiHalf = (lane & 16) != 0;
    unsigned rEA = hiHalf ? hE1A : hE0A;
    unsigned rOA = hiHalf ? hO1A : hO0A;
    unsigned rEB = hiHalf ? hE1B : hE0B;
    unsigned rOB = hiHalf ? hO1B : hO0B;
    unsigned rEC = hiHalf ? hE1C : hE0C;
    unsigned rOC = hiHalf ? hO1C : hO0C;
    float fbase = hiHalf ? 8.0f : 0.0f;
    int CEA = 0, CEB = 0, CEC = 0;
    #pragma unroll
    for (int m = 0; m < 8; m++) {
        float lm  = __fadd_rn(fbase, (float)m);
        float amA = fabsf(__fmaf_rn(lm, sA, mnA));
        float amB = fabsf(__fmaf_rn(lm, sB, mnB));
        float amC = fabsf(__fmaf_rn(lm, sC, mnC));
        unsigned rrA = (m & 1) ? rOA : rEA;
        unsigned rrB = (m & 1) ? rOB : rEB;
        unsigned rrC = (m & 1) ? rOC : rEC;
        int cmA = __byte_perm(rrA, 0u, 0x4440 | (m >> 1));
        int cmB = __byte_perm(rrB, 0u, 0x4440 | (m >> 1));
        int cmC = __byte_perm(rrC, 0u, 0x4440 | (m >> 1));
        if (amA <= alvA) CEA += cmA;
        if (amB <= alvB) CEB += cmB;
        if (amC <= alvC) CEC += cmC;
    }
    CEA += __shfl_xor_sync(WFULL, CEA, 16);
    CEB += __shfl_xor_sync(WFULL, CEB, 16);
    CEC += __shfl_xor_sync(WFULL, CEC, 16);

    // t = min alv among levels with Cle >= 64 (alv >= 0: bits order-isomorphic).
    int keyA = (CEA >= 64) ? __float_as_int(alvA) : 0x7fffffff;
    int keyB = (CEB >= 64) ? __float_as_int(alvB) : 0x7fffffff;
    int keyC = (CEC >= 64) ? __float_as_int(alvC) : 0x7fffffff;
    float tA = __int_as_float(redux_min_i(keyA));
    float tB = __int_as_float(redux_min_i(keyB));
    float tC = __int_as_float(redux_min_i(keyC));
    int CbA = redux_max_i((alvA == tA) ? CEA : 0);
    int CbB = redux_max_i((alvB == tB) ? CEB : 0);
    int CbC = redux_max_i((alvC == tC) ? CEC : 0);

    // Per-element: |e_k| is bit-identical to its level's alv (same FMA).
    int eqA0 = (fabsf(eA0) == tA), eqB0 = (fabsf(eB0) == tB), eqC0 = (fabsf(eC0) == tC);
    int eqA1 = (fabsf(eA1) == tA), eqB1 = (fabsf(eB1) == tB), eqC1 = (fabsf(eC1) == tC);
    int eqA2 = (fabsf(eA2) == tA), eqB2 = (fabsf(eB2) == tB), eqC2 = (fabsf(eC2) == tC);
    int eqA3 = (fabsf(eA3) == tA), eqB3 = (fabsf(eB3) == tB), eqC3 = (fabsf(eC3) == tC);
    unsigned BA0 = __ballot_sync(WFULL, eqA0), BB0 = __ballot_sync(WFULL, eqB0), BC0 = __ballot_sync(WFULL, eqC0);
    unsigned BA1 = __ballot_sync(WFULL, eqA1), BB1 = __ballot_sync(WFULL, eqB1), BC1 = __ballot_sync(WFULL, eqC1);
    unsigned BA2 = __ballot_sync(WFULL, eqA2), BB2 = __ballot_sync(WFULL, eqB2), BC2 = __ballot_sync(WFULL, eqC2);
    unsigned BA3 = __ballot_sync(WFULL, eqA3), BB3 = __ballot_sync(WFULL, eqB3), BC3 = __ballot_sync(WFULL, eqC3);
    unsigned below = (1u << lane) - 1u;
    int preA = __popc(BA0 & below) + __popc(BA1 & below)
             + __popc(BA2 & below) + __popc(BA3 & below);
    int preB = __popc(BB0 & below) + __popc(BB1 & below)
             + __popc(BB2 & below) + __popc(BB3 & below);
    int preC = __popc(BC0 & below) + __popc(BC1 & below)
             + __popc(BC2 & below) + __popc(BC3 & below);

    // E = #elements equal to t (full ballots already available).
    int EA = __popc(BA0) + __popc(BA1) + __popc(BA2) + __popc(BA3);
    int EB = __popc(BB0) + __popc(BB1) + __popc(BB2) + __popc(BB3);
    int EC = __popc(BC0) + __popc(BC1) + __popc(BC2) + __popc(BC3);
    int needA = 64 - CbA + EA;
    int needB = 64 - CbB + EB;
    int needC = 64 - CbC + EC;

    bool zA0 = (fabsf(eA0) < tA) || (eqA0 && (preA                      < needA));
    bool zA1 = (fabsf(eA1) < tA) || (eqA1 && (preA + eqA0               < needA));
    bool zA2 = (fabsf(eA2) < tA) || (eqA2 && (preA + eqA0 + eqA1        < needA));
    bool zA3 = (fabsf(eA3) < tA) || (eqA3 && (preA + eqA0 + eqA1 + eqA2 < needA));
    bool zB0 = (fabsf(eB0) < tB) || (eqB0 && (preB                      < needB));
    bool zB1 = (fabsf(eB1) < tB) || (eqB1 && (preB + eqB0               < needB));
    bool zB2 = (fabsf(eB2) < tB) || (eqB2 && (preB + eqB0 + eqB1        < needB));
    bool zB3 = (fabsf(eB3) < tB) || (eqB3 && (preB + eqB0 + eqB1 + eqB2 < needB));
    bool zC0 = (fabsf(eC0) < tC) || (eqC0 && (preC                      < needC));
    bool zC1 = (fabsf(eC1) < tC) || (eqC1 && (preC + eqC0               < needC));
    bool zC2 = (fabsf(eC2) < tC) || (eqC2 && (preC + eqC0 + eqC1        < needC));
    bool zC3 = (fabsf(eC3) < tC) || (eqC3 && (preC + eqC0 + eqC1 + eqC2 < needC));

    float4 oA, oB, oC;
    oA.x = __fadd_rn(bb.x, zA0 ? 0.0f : eA0);
    oA.y = __fadd_rn(bb.y, zA1 ? 0.0f : eA1);
    oA.z = __fadd_rn(bb.z, zA2 ? 0.0f : eA2);
    oA.w = __fadd_rn(bb.w, zA3 ? 0.0f : eA3);
    oB.x = __fadd_rn(bb.x, zB0 ? 0.0f : eB0);
    oB.y = __fadd_rn(bb.y, zB1 ? 0.0f : eB1);
    oB.z = __fadd_rn(bb.z, zB2 ? 0.0f : eB2);
    oB.w = __fadd_rn(bb.w, zB3 ? 0.0f : eB3);
    oC.x = __fadd_rn(bb.x, zC0 ? 0.0f : eC0);
    oC.y = __fadd_rn(bb.y, zC1 ? 0.0f : eC1);
    oC.z = __fadd_rn(bb.z, zC2 ? 0.0f : eC2);
    oC.w = __fadd_rn(bb.w, zC3 ? 0.0f : eC3);
    out4[ia] = oA;
    out4[ib] = oB;
    out4[ic] = oC;
}

extern "C" void kernel_launch(void* const* d_in, const int* in_sizes, int n_in,
                              void* d_out, int out_size) {
    const float* feat = (const float*)d_in[0];
    float* out = (float*)d_out;
    // k1: 8192 warps x 2 base rows = 16384 bases (written into out row-0 slots).
    kvq_base_kernel<<<1024, 256>>>(feat, out);
    // k2: 81920 warps; warp j of chunk c handles rows 1+j, 6+j, 11+j (ILP 3).
    kvq_diff_kernel<<<10240, 256>>>(feat, out);
}

// round 13
// speedup vs baseline: 1.0062x; 1.0062x over previous
#include <cuda_runtime.h>
#include <cstdint>

// KVQuantizer: feat [1, 32, 8192, 128] f32 -> same shape.
// Per chunk of 16 tokens (per head): row0 -> 8-bit asym quant (base);
// rows 1..15: diff = x - base_deq, 4-bit asym quant, zero the 64
// smallest-|deq| per 128-group with lowest-index tie-break, out = base + pruned.
// Bit-matches XLA:GPU: f32 divide -> div.full.f32, deq = fma(q,s,mn), rint.
// R13: single fused kernel (each warp recomputes its chunk's base inline,
// warp j==0 writes row 0); Cle scan accumulates in float on the fma pipe via
// PRMT magic-number byte->float extraction; E via lane-31 shuffle.

#define WFULL 0xFFFFFFFFu

__device__ __forceinline__ float div_full(float a, float b) {
    float r;
    asm("div.full.f32 %0, %1, %2;" : "=f"(r) : "f"(a), "f"(b));
    return r;
}
__device__ __forceinline__ int f2key(float x) {
    int u = __float_as_int(x);
    return u ^ ((u >> 31) & 0x7fffffff);
}
__device__ __forceinline__ float key2f(int k) {
    return __int_as_float(k ^ ((k >> 31) & 0x7fffffff));
}
__device__ __forceinline__ int redux_min_i(int v) {
    int r; asm("redux.sync.min.s32 %0, %1, 0xffffffff;" : "=r"(r) : "r"(v)); return r;
}
__device__ __forceinline__ int redux_max_i(int v) {
    int r; asm("redux.sync.max.s32 %0, %1, 0xffffffff;" : "=r"(r) : "r"(v)); return r;
}
__device__ __forceinline__ unsigned redux_add_u(unsigned v) {
    unsigned r; asm("redux.sync.add.u32 %0, %1, 0xffffffff;" : "=r"(r) : "r"(v)); return r;
}
__device__ __forceinline__ float warp_min_f(float x) { return key2f(redux_min_i(f2key(x))); }
__device__ __forceinline__ float warp_max_f(float x) { return key2f(redux_max_i(f2key(x))); }

__device__ __forceinline__ float quant_deq(float x, float mn, float s, float qmax, float& qf) {
    float t = div_full(__fsub_rn(x, mn), s);
    qf = fminf(fmaxf(rintf(t), 0.0f), qmax);
    return __fmaf_rn(qf, s, mn);
}

// Extract byte k of rr as an exact float in [0,255]: PRMT builds 0x4B0000xx
// (= 2^23 + byte), FADD subtracts the magic. One alu op + one fma op.
__device__ __forceinline__ float byte_as_float(unsigned rr, int k) {
    unsigned bits = __byte_perm(rr, 0x4B000000u, 0x7440u | (unsigned)k);
    return __fadd_rn(__int_as_float(bits), -8388608.0f);
}

// Warp handles rows 1+j, 6+j, 11+j (j = flat%5) of chunk flat/5; base row
// recomputed inline from in row 0 (bit-identical in all 5 warps); warp j==0
// also writes the row-0 output (which is exactly base_deq).
__global__ __launch_bounds__(256)
void kvq_kernel(const float* __restrict__ in, float* __restrict__ out) {
    int flat = (blockIdx.x << 3) + (threadIdx.x >> 5);   // [0, 81920)
    int lane = threadIdx.x & 31;
    int c = flat / 5;                   // chunk index [0, 16384)
    int j = flat - c * 5;               // warp slot 0..4

    const float4* in4  = reinterpret_cast<const float4*>(in);
    float4*       out4 = reinterpret_cast<float4*>(out);
    unsigned c0 = ((unsigned)c << 9) | (unsigned)lane;    // chunk row0
    unsigned ia = c0 + (((unsigned)j +  1u) << 5);        // row 1+j
    unsigned ib = c0 + (((unsigned)j +  6u) << 5);        // row 6+j
    unsigned ic = c0 + (((unsigned)j + 11u) << 5);        // row 11+j

    // Issue all loads up front.
    float4 v0 = in4[c0];
    float4 vA = in4[ia];
    float4 vB = in4[ib];
    float4 vC = in4[ic];

    // ---- Base row (8-bit quant of row 0), recomputed per warp ----
    float mn0 = warp_min_f(fminf(fminf(v0.x, v0.y), fminf(v0.z, v0.w)));
    float mx0 = warp_max_f(fmaxf(fmaxf(v0.x, v0.y), fmaxf(v0.z, v0.w)));
    float s0  = fmaxf(div_full(__fsub_rn(mx0, mn0), 255.0f), 1e-5f);
    float qf;
    float4 bb;
    bb.x = quant_deq(v0.x, mn0, s0, 255.0f, qf);
    bb.y = quant_deq(v0.y, mn0, s0, 255.0f, qf);
    bb.z = quant_deq(v0.z, mn0, s0, 255.0f, qf);
    bb.w = quant_deq(v0.w, mn0, s0, 255.0f, qf);
    // Row 0 output is exactly base_deq (zero diff quantizes to exactly 0).
    if (j == 0) out4[c0] = bb;

    // ---- Three independent diff rows (A, B, C), interleaved ----
    float dA0 = __fsub_rn(vA.x, bb.x), dB0 = __fsub_rn(vB.x, bb.x), dC0 = __fsub_rn(vC.x, bb.x);
    float dA1 = __fsub_rn(vA.y, bb.y), dB1 = __fsub_rn(vB.y, bb.y), dC1 = __fsub_rn(vC.y, bb.y);
    float dA2 = __fsub_rn(vA.z, bb.z), dB2 = __fsub_rn(vB.z, bb.z), dC2 = __fsub_rn(vC.z, bb.z);
    float dA3 = __fsub_rn(vA.w, bb.w), dB3 = __fsub_rn(vB.w, bb.w), dC3 = __fsub_rn(vC.w, bb.w);

    float mnA = warp_min_f(fminf(fminf(dA0, dA1), fminf(dA2, dA3)));
    float mnB = warp_min_f(fminf(fminf(dB0, dB1), fminf(dB2, dB3)));
    float mnC = warp_min_f(fminf(fminf(dC0, dC1), fminf(dC2, dC3)));
    float mxA = warp_max_f(fmaxf(fmaxf(dA0, dA1), fmaxf(dA2, dA3)));
    float mxB = warp_max_f(fmaxf(fmaxf(dB0, dB1), fmaxf(dB2, dB3)));
    float mxC = warp_max_f(fmaxf(fmaxf(dC0, dC1), fmaxf(dC2, dC3)));
    float sA  = fmaxf(div_full(__fsub_rn(mxA, mnA), 15.0f), 1e-5f);
    float sB  = fmaxf(div_full(__fsub_rn(mxB, mnB), 15.0f), 1e-5f);
    float sC  = fmaxf(div_full(__fsub_rn(mxC, mnC), 15.0f), 1e-5f);

    float qA0f, qA1f, qA2f, qA3f, qB0f, qB1f, qB2f, qB3f, qC0f, qC1f, qC2f, qC3f;
    float eA0 = quant_deq(dA0, mnA, sA, 15.0f, qA0f);
    float eB0 = quant_deq(dB0, mnB, sB, 15.0f, qB0f);
    float eC0 = quant_deq(dC0, mnC, sC, 15.0f, qC0f);
    float eA1 = quant_deq(dA1, mnA, sA, 15.0f, qA1f);
    float eB1 = quant_deq(dB1, mnB, sB, 15.0f, qB1f);
    float eC1 = quant_deq(dC1, mnC, sC, 15.0f, qC1f);
    float eA2 = quant_deq(dA2, mnA, sA, 15.0f, qA2f);
    float eB2 = quant_deq(dB2, mnB, sB, 15.0f, qB2f);
    float eC2 = quant_deq(dC2, mnC, sC, 15.0f, qC2f);
    float eA3 = quant_deq(dA3, mnA, sA, 15.0f, qA3f);
    float eB3 = quant_deq(dB3, mnB, sB, 15.0f, qB3f);
    float eC3 = quant_deq(dC3, mnC, sC, 15.0f, qC3f);
    int qA0 = (int)qA0f, qA1 = (int)qA1f, qA2 = (int)qA2f, qA3 = (int)qA3f;
    int qB0 = (int)qB0f, qB1 = (int)qB1f, qB2 = (int)qB2f, qB3 = (int)qB3f;
    int qC0 = (int)qC0f, qC1 = (int)qC1f, qC2 = (int)qC2f, qC3 = (int)qC3f;

    // ---- Histograms: unpredicated u64 nibble accumulators ----
    unsigned long long hhA = (1ULL << (qA0 << 2)) + (1ULL << (qA1 << 2))
                           + (1ULL << (qA2 << 2)) + (1ULL << (qA3 << 2));
    unsigned long long hhB = (1ULL << (qB0 << 2)) + (1ULL << (qB1 << 2))
                           + (1ULL << (qB2 << 2)) + (1ULL << (qB3 << 2));
    unsigned long long hhC = (1ULL << (qC0 << 2)) + (1ULL << (qC1 << 2))
                           + (1ULL << (qC2 << 2)) + (1ULL << (qC3 << 2));
    unsigned loA = (unsigned)hhA, hiA = (unsigned)(hhA >> 32);
    unsigned loB = (unsigned)hhB, hiB = (unsigned)(hhB >> 32);
    unsigned loC = (unsigned)hhC, hiC = (unsigned)(hhC >> 32);
    unsigned hE0A = redux_add_u( loA       & 0x0F0F0F0Fu);
    unsigned hE0B = redux_add_u( loB       & 0x0F0F0F0Fu);
    unsigned hE0C = redux_add_u( loC       & 0x0F0F0F0Fu);
    unsigned hO0A = redux_add_u((loA >> 4) & 0x0F0F0F0Fu);
    unsigned hO0B = redux_add_u((loB >> 4) & 0x0F0F0F0Fu);
    unsigned hO0C = redux_add_u((loC >> 4) & 0x0F0F0F0Fu);
    unsigned hE1A = redux_add_u( hiA       & 0x0F0F0F0Fu);
    unsigned hE1B = redux_add_u( hiB       & 0x0F0F0F0Fu);
    unsigned hE1C = redux_add_u( hiC       & 0x0F0F0F0Fu);
    unsigned hO1A = redux_add_u((hiA >> 4) & 0x0F0F0F0Fu);
    unsigned hO1B = redux_add_u((hiB >> 4) & 0x0F0F0F0Fu);
    unsigned hO1C = redux_add_u((hiC >> 4) & 0x0F0F0F0Fu);

    // Mirrored levels: lanes l and l+16 both own level (l & 15).
    int lvl = lane & 15;
    float alvA = fabsf(__fmaf_rn((float)lvl, sA, mnA));
    float alvB = fabsf(__fmaf_rn((float)lvl, sB, mnB));
    float alvC = fabsf(__fmaf_rn((float)lvl, sC, mnC));

    // Halved Cle scan: lanes<16 scan levels [0,8), lanes>=16 [8,16).
    // Counts accumulated as exact floats on the fma pipe.
    bool hiHalf = (lane & 16) != 0;
    unsigned rEA = hiHalf ? hE1A : hE0A;
    unsigned rOA = hiHalf ? hO1A : hO0A;
    unsigned rEB = hiHalf ? hE1B : hE0B;
    unsigned rOB = hiHalf ? hO1B : hO0B;
    unsigned rEC = hiHalf ? hE1C : hE0C;
    unsigned rOC = hiHalf ? hO1C : hO0C;
    float fbase = hiHalf ? 8.0f : 0.0f;
    float CEA = 0.0f, CEB = 0.0f, CEC = 0.0f;
    #pragma unroll
    for (int m = 0; m < 8; m++) {
        float lm  = __fadd_rn(fbase, (float)m);
        float amA = fabsf(__fmaf_rn(lm, sA, mnA));
        float amB = fabsf(__fmaf_rn(lm, sB, mnB));
        float amC = fabsf(__fmaf_rn(lm, sC, mnC));
        float cmA = byte_as_float((m & 1) ? rOA : rEA, m >> 1);
        float cmB = byte_as_float((m & 1) ? rOB : rEB, m >> 1);
        float cmC = byte_as_float((m & 1) ? rOC : rEC, m >> 1);
        if (amA <= alvA) CEA = __fadd_rn(CEA, cmA);
        if (amB <= alvB) CEB = __fadd_rn(CEB, cmB);
        if (amC <= alvC) CEC = __fadd_rn(CEC, cmC);
    }
    CEA = __fadd_rn(CEA, __shfl_xor_sync(WFULL, CEA, 16));
    CEB = __fadd_rn(CEB, __shfl_xor_sync(WFULL, CEB, 16));
    CEC = __fadd_rn(CEC, __shfl_xor_sync(WFULL, CEC, 16));

    // t = min alv among levels with Cle >= 64 (alv >= 0: bits order-isomorphic).
    int keyA = (CEA >= 64.0f) ? __float_as_int(alvA) : 0x7fffffff;
    int keyB = (CEB >= 64.0f) ? __float_as_int(alvB) : 0x7fffffff;
    int keyC = (CEC >= 64.0f) ? __float_as_int(alvC) : 0x7fffffff;
    float tA = __int_as_float(redux_min_i(keyA));
    float tB = __int_as_float(redux_min_i(keyB));
    float tC = __int_as_float(redux_min_i(keyC));
    // Cle at the boundary (CEf >= 64 > 0, nonneg float bits order as ints).
    float CbA = __int_as_float(redux_max_i((alvA == tA) ? __float_as_int(CEA) : 0));
    float CbB = __int_as_float(redux_max_i((alvB == tB) ? __float_as_int(CEB) : 0));
    float CbC = __int_as_float(redux_max_i((alvC == tC) ? __float_as_int(CEC) : 0));

    // Per-element: |e_k| is bit-identical to its level's alv (same FMA).
    int eqA0 = (fabsf(eA0) == tA), eqB0 = (fabsf(eB0) == tB), eqC0 = (fabsf(eC0) == tC);
    int eqA1 = (fabsf(eA1) == tA), eqB1 = (fabsf(eB1) == tB), eqC1 = (fabsf(eC1) == tC);
    int eqA2 = (fabsf(eA2) == tA), eqB2 = (fabsf(eB2) == tB), eqC2 = (fabsf(eC2) == tC);
    int eqA3 = (fabsf(eA3) == tA), eqB3 = (fabsf(eB3) == tB), eqC3 = (fabsf(eC3) == tC);
    unsigned BA0 = __ballot_sync(WFULL, eqA0), BB0 = __ballot_sync(WFULL, eqB0), BC0 = __ballot_sync(WFULL, eqC0);
    unsigned BA1 = __ballot_sync(WFULL, eqA1), BB1 = __ballot_sync(WFULL, eqB1), BC1 = __ballot_sync(WFULL, eqC1);
    unsigned BA2 = __ballot_sync(WFULL, eqA2), BB2 = __ballot_sync(WFULL, eqB2), BC2 = __ballot_sync(WFULL, eqC2);
    unsigned BA3 = __ballot_sync(WFULL, eqA3), BB3 = __ballot_sync(WFULL, eqB3), BC3 = __ballot_sync(WFULL, eqC3);
    unsigned below = (1u << lane) - 1u;
    int preA = __popc(BA0 & below) + __popc(BA1 & below)
             + __popc(BA2 & below) + __popc(BA3 & below);
    int preB = __popc(BB0 & below) + __popc(BB1 & below)
             + __popc(BB2 & below) + __popc(BB3 & below);
    int preC = __popc(BC0 & below) + __popc(BC1 & below)
             + __popc(BC2 & below) + __popc(BC3 & below);

    // E = total elements equal to t = lane31's (pre + own eq sum).
    int EA = __shfl_sync(WFULL, preA + eqA0 + eqA1 + eqA2 + eqA3, 31);
    int EB = __shfl_sync(WFULL, preB + eqB0 + eqB1 + eqB2 + eqB3, 31);
    int EC = __shfl_sync(WFULL, preC + eqC0 + eqC1 + eqC2 + eqC3, 31);
    int needA = 64 - __float2int_rn(CbA) + EA;
    int needB = 64 - __float2int_rn(CbB) + EB;
    int needC = 64 - __float2int_rn(CbC) + EC;

    bool zA0 = (fabsf(eA0) < tA) || (eqA0 && (preA                      < needA));
    bool zA1 = (fabsf(eA1) < tA) || (eqA1 && (preA + eqA0               < needA));
    bool zA2 = (fabsf(eA2) < tA) || (eqA2 && (preA + eqA0 + eqA1        < needA));
    bool zA3 = (fabsf(eA3) < tA) || (eqA3 && (preA + eqA0 + eqA1 + eqA2 < needA));
    bool zB0 = (fabsf(eB0) < tB) || (eqB0 && (preB                      < needB));
    bool zB1 = (fabsf(eB1) < tB) || (eqB1 && (preB + eqB0               < needB));
    bool zB2 = (fabsf(eB2) < tB) || (eqB2 && (preB + eqB0 + eqB1        < needB));
    bool zB3 = (fabsf(eB3) < tB) || (eqB3 && (preB + eqB0 + eqB1 + eqB2 < needB));
    bool zC0 = (fabsf(eC0) < tC) || (eqC0 && (preC                      < needC));
    bool zC1 = (fabsf(eC1) < tC) || (eqC1 && (preC + eqC0               < needC));
    bool zC2 = (fabsf(eC2) < tC) || (eqC2 && (preC + eqC0 + eqC1        < needC));
    bool zC3 = (fabsf(eC3) < tC) || (eqC3 && (preC + eqC0 + eqC1 + eqC2 < needC));

    float4 oA, oB, oC;
    oA.x = __fadd_rn(bb.x, zA0 ? 0.0f : eA0);
    oA.y = __fadd_rn(bb.y, zA1 ? 0.0f : eA1);
    oA.z = __fadd_rn(bb.z, zA2 ? 0.0f : eA2);
    oA.w = __fadd_rn(bb.w, zA3 ? 0.0f : eA3);
    oB.x = __fadd_rn(bb.x, zB0 ? 0.0f : eB0);
    oB.y = __fadd_rn(bb.y, zB1 ? 0.0f : eB1);
    oB.z = __fadd_rn(bb.z, zB2 ? 0.0f : eB2);
    oB.w = __fadd_rn(bb.w, zB3 ? 0.0f : eB3);
    oC.x = __fadd_rn(bb.x, zC0 ? 0.0f : eC0);
    oC.y = __fadd_rn(bb.y, zC1 ? 0.0f : eC1);
    oC.z = __fadd_rn(bb.z, zC2 ? 0.0f : eC2);
    oC.w = __fadd_rn(bb.w, zC3 ? 0.0f : eC3);
    out4[ia] = oA;
    out4[ib] = oB;
    out4[ic] = oC;
}

extern "C" void kernel_launch(void* const* d_in, const int* in_sizes, int n_in,
                              void* d_out, int out_size) {
    const float* feat = (const float*)d_in[0];
    float* out = (float*)d_out;
    // 81920 warps; warp j of chunk c handles rows 1+j, 6+j, 11+j (ILP 3),
    // recomputes the chunk base inline, and warp j==0 writes row 0.
    kvq_kernel<<<10240, 256>>>(feat, out);
}

// round 14
// speedup vs baseline: 1.0325x; 1.0261x over previous
#include <cuda_runtime.h>
#include <cstdint>

// KVQuantizer: feat [1, 32, 8192, 128] f32 -> same shape.
// Per chunk of 16 tokens (per head): row0 -> 8-bit asym quant (base);
// rows 1..15: diff = x - base_deq, 4-bit asym quant, zero the 64
// smallest-|deq| per 128-group with lowest-index tie-break, out = base + pruned.
// Bit-matches XLA:GPU: f32 divide -> div.full.f32, deq = fma(q,s,mn), rint.
// R14: warp-per-chunk -- base computed ONCE per chunk (was 5x redundant),
// then 5 phases x 3 rows with the R13 ILP-3 body; next-phase rows
// software-prefetched; #pragma unroll 1 keeps the body I-cache resident.

#define WFULL 0xFFFFFFFFu

__device__ __forceinline__ float div_full(float a, float b) {
    float r;
    asm("div.full.f32 %0, %1, %2;" : "=f"(r) : "f"(a), "f"(b));
    return r;
}
__device__ __forceinline__ int f2key(float x) {
    int u = __float_as_int(x);
    return u ^ ((u >> 31) & 0x7fffffff);
}
__device__ __forceinline__ float key2f(int k) {
    return __int_as_float(k ^ ((k >> 31) & 0x7fffffff));
}
__device__ __forceinline__ int redux_min_i(int v) {
    int r; asm("redux.sync.min.s32 %0, %1, 0xffffffff;" : "=r"(r) : "r"(v)); return r;
}
__device__ __forceinline__ int redux_max_i(int v) {
    int r; asm("redux.sync.max.s32 %0, %1, 0xffffffff;" : "=r"(r) : "r"(v)); return r;
}
__device__ __forceinline__ unsigned redux_add_u(unsigned v) {
    unsigned r; asm("redux.sync.add.u32 %0, %1, 0xffffffff;" : "=r"(r) : "r"(v)); return r;
}
__device__ __forceinline__ float warp_min_f(float x) { return key2f(redux_min_i(f2key(x))); }
__device__ __forceinline__ float warp_max_f(float x) { return key2f(redux_max_i(f2key(x))); }

__device__ __forceinline__ float quant_deq(float x, float mn, float s, float qmax, float& qf) {
    float t = div_full(__fsub_rn(x, mn), s);
    qf = fminf(fmaxf(rintf(t), 0.0f), qmax);
    return __fmaf_rn(qf, s, mn);
}

// Extract byte k of rr as an exact float in [0,255]: PRMT builds 0x4B0000xx
// (= 2^23 + byte), FADD subtracts the magic.
__device__ __forceinline__ float byte_as_float(unsigned rr, int k) {
    unsigned bits = __byte_perm(rr, 0x4B000000u, 0x7440u | (unsigned)k);
    return __fadd_rn(__int_as_float(bits), -8388608.0f);
}

// Process 3 independent diff rows (shared base bb), returning pruned outputs.
__device__ __forceinline__ void process3(
    float4 vA, float4 vB, float4 vC, float4 bb, int lane,
    float4& oA, float4& oB, float4& oC)
{
    float dA0 = __fsub_rn(vA.x, bb.x), dB0 = __fsub_rn(vB.x, bb.x), dC0 = __fsub_rn(vC.x, bb.x);
    float dA1 = __fsub_rn(vA.y, bb.y), dB1 = __fsub_rn(vB.y, bb.y), dC1 = __fsub_rn(vC.y, bb.y);
    float dA2 = __fsub_rn(vA.z, bb.z), dB2 = __fsub_rn(vB.z, bb.z), dC2 = __fsub_rn(vC.z, bb.z);
    float dA3 = __fsub_rn(vA.w, bb.w), dB3 = __fsub_rn(vB.w, bb.w), dC3 = __fsub_rn(vC.w, bb.w);

    float mnA = warp_min_f(fminf(fminf(dA0, dA1), fminf(dA2, dA3)));
    float mnB = warp_min_f(fminf(fminf(dB0, dB1), fminf(dB2, dB3)));
    float mnC = warp_min_f(fminf(fminf(dC0, dC1), fminf(dC2, dC3)));
    float mxA = warp_max_f(fmaxf(fmaxf(dA0, dA1), fmaxf(dA2, dA3)));
    float mxB = warp_max_f(fmaxf(fmaxf(dB0, dB1), fmaxf(dB2, dB3)));
    float mxC = warp_max_f(fmaxf(fmaxf(dC0, dC1), fmaxf(dC2, dC3)));
    float sA  = fmaxf(div_full(__fsub_rn(mxA, mnA), 15.0f), 1e-5f);
    float sB  = fmaxf(div_full(__fsub_rn(mxB, mnB), 15.0f), 1e-5f);
    float sC  = fmaxf(div_full(__fsub_rn(mxC, mnC), 15.0f), 1e-5f);

    float qA0f, qA1f, qA2f, qA3f, qB0f, qB1f, qB2f, qB3f, qC0f, qC1f, qC2f, qC3f;
    float eA0 = quant_deq(dA0, mnA, sA, 15.0f, qA0f);
    float eB0 = quant_deq(dB0, mnB, sB, 15.0f, qB0f);
    float eC0 = quant_deq(dC0, mnC, sC, 15.0f, qC0f);
    float eA1 = quant_deq(dA1, mnA, sA, 15.0f, qA1f);
    float eB1 = quant_deq(dB1, mnB, sB, 15.0f, qB1f);
    float eC1 = quant_deq(dC1, mnC, sC, 15.0f, qC1f);
    float eA2 = quant_deq(dA2, mnA, sA, 15.0f, qA2f);
    float eB2 = quant_deq(dB2, mnB, sB, 15.0f, qB2f);
    float eC2 = quant_deq(dC2, mnC, sC, 15.0f, qC2f);
    float eA3 = quant_deq(dA3, mnA, sA, 15.0f, qA3f);
    float eB3 = quant_deq(dB3, mnB, sB, 15.0f, qB3f);
    float eC3 = quant_deq(dC3, mnC, sC, 15.0f, qC3f);
    int qA0 = (int)qA0f, qA1 = (int)qA1f, qA2 = (int)qA2f, qA3 = (int)qA3f;
    int qB0 = (int)qB0f, qB1 = (int)qB1f, qB2 = (int)qB2f, qB3 = (int)qB3f;
    int qC0 = (int)qC0f, qC1 = (int)qC1f, qC2 = (int)qC2f, qC3 = (int)qC3f;

    // Histograms: unpredicated u64 nibble accumulators, redux per u32 half.
    unsigned long long hhA = (1ULL << (qA0 << 2)) + (1ULL << (qA1 << 2))
                           + (1ULL << (qA2 << 2)) + (1ULL << (qA3 << 2));
    unsigned long long hhB = (1ULL << (qB0 << 2)) + (1ULL << (qB1 << 2))
                           + (1ULL << (qB2 << 2)) + (1ULL << (qB3 << 2));
    unsigned long long hhC = (1ULL << (qC0 << 2)) + (1ULL << (qC1 << 2))
                           + (1ULL << (qC2 << 2)) + (1ULL << (qC3 << 2));
    unsigned loA = (unsigned)hhA, hiA = (unsigned)(hhA >> 32);
    unsigned loB = (unsigned)hhB, hiB = (unsigned)(hhB >> 32);
    unsigned loC = (unsigned)hhC, hiC = (unsigned)(hhC >> 32);
    unsigned hE0A = redux_add_u( loA       & 0x0F0F0F0Fu);
    unsigned hE0B = redux_add_u( loB       & 0x0F0F0F0Fu);
    unsigned hE0C = redux_add_u( loC       & 0x0F0F0F0Fu);
    unsigned hO0A = redux_add_u((loA >> 4) & 0x0F0F0F0Fu);
    unsigned hO0B = redux_add_u((loB >> 4) & 0x0F0F0F0Fu);
    unsigned hO0C = redux_add_u((loC >> 4) & 0x0F0F0F0Fu);
    unsigned hE1A = redux_add_u( hiA       & 0x0F0F0F0Fu);
    unsigned hE1B = redux_add_u( hiB       & 0x0F0F0F0Fu);
    unsigned hE1C = redux_add_u( hiC       & 0x0F0F0F0Fu);
    unsigned hO1A = redux_add_u((hiA >> 4) & 0x0F0F0F0Fu);
    unsigned hO1B = redux_add_u((hiB >> 4) & 0x0F0F0F0Fu);
    unsigned hO1C = redux_add_u((hiC >> 4) & 0x0F0F0F0Fu);

    // Mirrored levels: lanes l and l+16 both own level (l & 15).
    int lvl = lane & 15;
    float alvA = fabsf(__fmaf_rn((float)lvl, sA, mnA));
    float alvB = fabsf(__fmaf_rn((float)lvl, sB, mnB));
    float alvC = fabsf(__fmaf_rn((float)lvl, sC, mnC));

    // Halved Cle scan: lanes<16 scan levels [0,8), lanes>=16 [8,16).
    bool hiHalf = (lane & 16) != 0;
    unsigned rEA = hiHalf ? hE1A : hE0A;
    unsigned rOA = hiHalf ? hO1A : hO0A;
    unsigned rEB = hiHalf ? hE1B : hE0B;
    unsigned rOB = hiHalf ? hO1B : hO0B;
    unsigned rEC = hiHalf ? hE1C : hE0C;
    unsigned rOC = hiHalf ? hO1C : hO0C;
    float fbase = hiHalf ? 8.0f : 0.0f;
    float CEA = 0.0f, CEB = 0.0f, CEC = 0.0f;
    #pragma unroll
    for (int m = 0; m < 8; m++) {
        float lm  = __fadd_rn(fbase, (float)m);
        float amA = fabsf(__fmaf_rn(lm, sA, mnA));
        float amB = fabsf(__fmaf_rn(lm, sB, mnB));
        float amC = fabsf(__fmaf_rn(lm, sC, mnC));
        float cmA = byte_as_float((m & 1) ? rOA : rEA, m >> 1);
        float cmB = byte_as_float((m & 1) ? rOB : rEB, m >> 1);
        float cmC = byte_as_float((m & 1) ? rOC : rEC, m >> 1);
        if (amA <= alvA) CEA = __fadd_rn(CEA, cmA);
        if (amB <= alvB) CEB = __fadd_rn(CEB, cmB);
        if (amC <= alvC) CEC = __fadd_rn(CEC, cmC);
    }
    CEA = __fadd_rn(CEA, __shfl_xor_sync(WFULL, CEA, 16));
    CEB = __fadd_rn(CEB, __shfl_xor_sync(WFULL, CEB, 16));
    CEC = __fadd_rn(CEC, __shfl_xor_sync(WFULL, CEC, 16));

    // t = min alv among levels with Cle >= 64 (alv >= 0: bits order-isomorphic).
    int keyA = (CEA >= 64.0f) ? __float_as_int(alvA) : 0x7fffffff;
    int keyB = (CEB >= 64.0f) ? __float_as_int(alvB) : 0x7fffffff;
    int keyC = (CEC >= 64.0f) ? __float_as_int(alvC) : 0x7fffffff;
    float tA = __int_as_float(redux_min_i(keyA));
    float tB = __int_as_float(redux_min_i(keyB));
    float tC = __int_as_float(redux_min_i(keyC));
    float CbA = __int_as_float(redux_max_i((alvA == tA) ? __float_as_int(CEA) : 0));
    float CbB = __int_as_float(redux_max_i((alvB == tB) ? __float_as_int(CEB) : 0));
    float CbC = __int_as_float(redux_max_i((alvC == tC) ? __float_as_int(CEC) : 0));

    // Per-element: |e_k| is bit-identical to its level's alv (same FMA).
    int eqA0 = (fabsf(eA0) == tA), eqB0 = (fabsf(eB0) == tB), eqC0 = (fabsf(eC0) == tC);
    int eqA1 = (fabsf(eA1) == tA), eqB1 = (fabsf(eB1) == tB), eqC1 = (fabsf(eC1) == tC);
    int eqA2 = (fabsf(eA2) == tA), eqB2 = (fabsf(eB2) == tB), eqC2 = (fabsf(eC2) == tC);
    int eqA3 = (fabsf(eA3) == tA), eqB3 = (fabsf(eB3) == tB), eqC3 = (fabsf(eC3) == tC);
    unsigned BA0 = __ballot_sync(WFULL, eqA0), BB0 = __ballot_sync(WFULL, eqB0), BC0 = __ballot_sync(WFULL, eqC0);
    unsigned BA1 = __ballot_sync(WFULL, eqA1), BB1 = __ballot_sync(WFULL, eqB1), BC1 = __ballot_sync(WFULL, eqC1);
    unsigned BA2 = __ballot_sync(WFULL, eqA2), BB2 = __ballot_sync(WFULL, eqB2), BC2 = __ballot_sync(WFULL, eqC2);
    unsigned BA3 = __ballot_sync(WFULL, eqA3), BB3 = __ballot_sync(WFULL, eqB3), BC3 = __ballot_sync(WFULL, eqC3);
    unsigned below = (1u << lane) - 1u;
    int preA = __popc(BA0 & below) + __popc(BA1 & below)
             + __popc(BA2 & below) + __popc(BA3 & below);
    int preB = __popc(BB0 & below) + __popc(BB1 & below)
             + __popc(BB2 & below) + __popc(BB3 & below);
    int preC = __popc(BC0 & below) + __popc(BC1 & below)
             + __popc(BC2 & below) + __popc(BC3 & below);

    // E = total elements equal to t = lane31's (pre + own eq sum).
    int EA = __shfl_sync(WFULL, preA + eqA0 + eqA1 + eqA2 + eqA3, 31);
    int EB = __shfl_sync(WFULL, preB + eqB0 + eqB1 + eqB2 + eqB3, 31);
    int EC = __shfl_sync(WFULL, preC + eqC0 + eqC1 + eqC2 + eqC3, 31);
    int needA = 64 - __float2int_rn(CbA) + EA;
    int needB = 64 - __float2int_rn(CbB) + EB;
    int needC = 64 - __float2int_rn(CbC) + EC;

    bool zA0 = (fabsf(eA0) < tA) || (eqA0 && (preA                      < needA));
    bool zA1 = (fabsf(eA1) < tA) || (eqA1 && (preA + eqA0               < needA));
    bool zA2 = (fabsf(eA2) < tA) || (eqA2 && (preA + eqA0 + eqA1        < needA));
    bool zA3 = (fabsf(eA3) < tA) || (eqA3 && (preA + eqA0 + eqA1 + eqA2 < needA));
    bool zB0 = (fabsf(eB0) < tB) || (eqB0 && (preB                      < needB));
    bool zB1 = (fabsf(eB1) < tB) || (eqB1 && (preB + eqB0               < needB));
    bool zB2 = (fabsf(eB2) < tB) || (eqB2 && (preB + eqB0 + eqB1        < needB));
    bool zB3 = (fabsf(eB3) < tB) || (eqB3 && (preB + eqB0 + eqB1 + eqB2 < needB));
    bool zC0 = (fabsf(eC0) < tC) || (eqC0 && (preC                      < needC));
    bool zC1 = (fabsf(eC1) < tC) || (eqC1 && (preC + eqC0               < needC));
    bool zC2 = (fabsf(eC2) < tC) || (eqC2 && (preC + eqC0 + eqC1        < needC));
    bool zC3 = (fabsf(eC3) < tC) || (eqC3 && (preC + eqC0 + eqC1 + eqC2 < needC));

    oA.x = __fadd_rn(bb.x, zA0 ? 0.0f : eA0);
    oA.y = __fadd_rn(bb.y, zA1 ? 0.0f : eA1);
    oA.z = __fadd_rn(bb.z, zA2 ? 0.0f : eA2);
    oA.w = __fadd_rn(bb.w, zA3 ? 0.0f : eA3);
    oB.x = __fadd_rn(bb.x, zB0 ? 0.0f : eB0);
    oB.y = __fadd_rn(bb.y, zB1 ? 0.0f : eB1);
    oB.z = __fadd_rn(bb.z, zB2 ? 0.0f : eB2);
    oB.w = __fadd_rn(bb.w, zB3 ? 0.0f : eB3);
    oC.x = __fadd_rn(bb.x, zC0 ? 0.0f : eC0);
    oC.y = __fadd_rn(bb.y, zC1 ? 0.0f : eC1);
    oC.z = __fadd_rn(bb.z, zC2 ? 0.0f : eC2);
    oC.w = __fadd_rn(bb.w, zC3 ? 0.0f : eC3);
}

// Warp-per-chunk: base computed once, then 5 phases x 3 rows (prefetched).
__global__ __launch_bounds__(256)
void kvq_kernel(const float* __restrict__ in, float* __restrict__ out) {
    int wid  = (blockIdx.x << 3) + (threadIdx.x >> 5);   // chunk [0, 16384)
    int lane = threadIdx.x & 31;

    const float4* in4  = reinterpret_cast<const float4*>(in);
    float4*       out4 = reinterpret_cast<float4*>(out);
    unsigned c0 = ((unsigned)wid << 9) | (unsigned)lane;  // chunk row0

    // ---- Base row (8-bit quant of row 0), once per chunk ----
    float4 v0 = in4[c0];
    float mn0 = warp_min_f(fminf(fminf(v0.x, v0.y), fminf(v0.z, v0.w)));
    float mx0 = warp_max_f(fmaxf(fmaxf(v0.x, v0.y), fmaxf(v0.z, v0.w)));
    float s0  = fmaxf(div_full(__fsub_rn(mx0, mn0), 255.0f), 1e-5f);
    float qf;
    float4 bb;
    bb.x = quant_deq(v0.x, mn0, s0, 255.0f, qf);
    bb.y = quant_deq(v0.y, mn0, s0, 255.0f, qf);
    bb.z = quant_deq(v0.z, mn0, s0, 255.0f, qf);
    bb.w = quant_deq(v0.w, mn0, s0, 255.0f, qf);
    // Row 0 output is exactly base_deq (zero diff quantizes to exactly 0).
    out4[c0] = bb;

    // ---- 5 phases x 3 rows, next phase prefetched ----
    unsigned idx = c0 + 32u;               // row 1
    float4 vA = in4[idx];
    float4 vB = in4[idx + 32u];
    float4 vC = in4[idx + 64u];
    #pragma unroll 1
    for (int p = 0; p < 5; p++) {
        unsigned nidx = idx + 96u;
        float4 nA, nB, nC;
        if (p < 4) {
            nA = in4[nidx];
            nB = in4[nidx + 32u];
            nC = in4[nidx + 64u];
        }
        float4 oA, oB, oC;
        process3(vA, vB, vC, bb, lane, oA, oB, oC);
        out4[idx]       = oA;
        out4[idx + 32u] = oB;
        out4[idx + 64u] = oC;
        idx = nidx;
        vA = nA; vB = nB; vC = nC;
    }
}

extern "C" void kernel_launch(void* const* d_in, const int* in_sizes, int n_in,
                              void* d_out, int out_size) {
    const float* feat = (const float*)d_in[0];
    float* out = (float*)d_out;
    // 16384 chunks, one warp each; 8 warps (256 threads) per block.
    kvq_kernel<<<2048, 256>>>(feat, out);
}